// round 10
// baseline (speedup 1.0000x reference)
#include <cuda_runtime.h>
#include <math.h>

#define NN   250000
#define EE   1000000
#define BB   25
#define NX_  8
#define NY_  9
#define NCC  72
#define MM   1800
#define GRD  16
#define NOUTC 2
#define EPSB 1e-5f

typedef unsigned long long ull;

// ---------------- f32x2 packed-math helpers (sm_10x) --------------------------
__device__ __forceinline__ ull pack2(float x, float y) {
    ull r; asm("mov.b64 %0, {%1, %2};" : "=l"(r) : "f"(x), "f"(y)); return r;
}
__device__ __forceinline__ void unpack2(ull v, float& x, float& y) {
    asm("mov.b64 {%0, %1}, %2;" : "=f"(x), "=f"(y) : "l"(v));
}
__device__ __forceinline__ ull ffma2(ull a, ull b, ull c) {
    ull d; asm("fma.rn.f32x2 %0, %1, %2, %3;" : "=l"(d) : "l"(a), "l"(b), "l"(c)); return d;
}
__device__ __forceinline__ ull fmul2(ull a, ull b) {
    ull d; asm("mul.rn.f32x2 %0, %1, %2;" : "=l"(d) : "l"(a), "l"(b)); return d;
}
__device__ __forceinline__ ull fadd2(ull a, ull b) {
    ull d; asm("add.rn.f32x2 %0, %1, %2;" : "=l"(d) : "l"(a), "l"(b)); return d;
}

// ---------------- scratch (device globals; no allocation allowed) -------------
__device__ float d_xA[NN * 32];              // conv outputs (raw, pre-BN)
__device__ float d_xe[(size_t)EE * 16];      // edge-ordered BN'd src features (64MB)
__device__ int   d_deg[NN];
__device__ int   d_off[NN];                  // CSR offsets (block-partial; add pbase)
__device__ int   d_cur[NN];                  // fill cursors
__device__ int   d_part[1024];               // scan partials
__device__ int   d_pbase[1024];
__device__ int   d_esrc[EE];                 // CSR-ordered source node ids
__device__ __align__(16) float d_sbas[(size_t)EE * 8];  // CSR-ordered basis (32MB)
__device__ int   d_clu[NN];
__device__ float d_statsAll[5 * 64];         // per-conv [sum(C), sumsq(C)]
__device__ float d_xp[MM * 32];              // pooled features (max pooled)
__device__ float d_pp[MM * 3];               // pooled positions
__device__ int   d_cnt[MM];
__device__ unsigned char d_adj[MM * MM];
__device__ int   d_maxv;                     // float bits (non-negative)
__device__ int   d_nm;                       // number of non-empty cells
__device__ float d_pstats[64];               // pooled BN stats
__device__ float d_pz[MM * 8 * 32];          // pooled per-node projections
__device__ float d_xt[MM * 32];              // pooled conv raw output
__device__ float d_xu[MM * 32];              // pooled conv post-BN output
__device__ float d_xg[BB * GRD * 32];        // MaxPoolingX output

// ---------------- helpers ----------------------------------------------------
__device__ __forceinline__ int csr_off(int d) {
    return d_off[d] + d_pbase[d >> 8];
}
__device__ __forceinline__ int csr_end(int d) {
    return (d == NN - 1) ? EE : csr_off(d + 1);
}

__device__ __forceinline__ void basis8(float p0, float p1, float p2, float* b) {
    p0 = fminf(fmaxf(p0, 0.f), 1.f);
    p1 = fminf(fmaxf(p1, 0.f), 1.f);
    p2 = fminf(fmaxf(p2, 0.f), 1.f);
    float q0 = 1.f - p0, q1 = 1.f - p1, q2 = 1.f - p2;
    b[0] = q0 * q1 * q2; b[1] = p0 * q1 * q2;
    b[2] = q0 * p1 * q2; b[3] = p0 * p1 * q2;
    b[4] = q0 * q1 * p2; b[5] = p0 * q1 * p2;
    b[6] = q0 * p1 * p2; b[7] = p0 * p1 * p2;
}

__device__ __forceinline__ void atomicMaxFloatPos(float* addr, float v) {
    atomicMax(reinterpret_cast<int*>(addr), __float_as_int(v));
}

// ---------------- degree + CSR build -----------------------------------------
__global__ void k_deg(const int* __restrict__ dst) {
    int e = blockIdx.x * blockDim.x + threadIdx.x;
    if (e < EE) atomicAdd(&d_deg[dst[e]], 1);
}

__global__ void k_scanA() {  // 256 threads/block; also zeroes d_cur
    __shared__ int sm[256];
    int i = blockIdx.x * 256 + threadIdx.x;
    int v = (i < NN) ? d_deg[i] : 0;
    if (i < NN) d_cur[i] = 0;
    sm[threadIdx.x] = v;
    __syncthreads();
    for (int off = 1; off < 256; off <<= 1) {
        int t = (threadIdx.x >= off) ? sm[threadIdx.x - off] : 0;
        __syncthreads();
        sm[threadIdx.x] += t;
        __syncthreads();
    }
    if (i < NN) d_off[i] = sm[threadIdx.x] - v;  // exclusive within block
    if (threadIdx.x == 255) d_part[blockIdx.x] = sm[255];
}

__global__ void k_scanB(int nparts) {  // 1 block, 1024 threads
    __shared__ int sm[1024];
    int v = (threadIdx.x < nparts) ? d_part[threadIdx.x] : 0;
    sm[threadIdx.x] = v;
    __syncthreads();
    for (int off = 1; off < 1024; off <<= 1) {
        int t = (threadIdx.x >= off) ? sm[threadIdx.x - off] : 0;
        __syncthreads();
        sm[threadIdx.x] += t;
        __syncthreads();
    }
    if (threadIdx.x < nparts) d_pbase[threadIdx.x] = sm[threadIdx.x] - v;
}

__global__ void k_fill(const int* __restrict__ src, const int* __restrict__ dst,
                       const float* __restrict__ ea) {
    int e = blockIdx.x * blockDim.x + threadIdx.x;
    if (e < 5 * 64) d_statsAll[e] = 0.f;     // zero all conv BN stats
    if (e >= EE) return;
    int d = dst[e];
    int slot = csr_off(d) + atomicAdd(&d_cur[d], 1);
    d_esrc[slot] = src[e];
    float bs[8];
    basis8(ea[3 * e + 0], ea[3 * e + 1], ea[3 * e + 2], bs);
    float4* p = reinterpret_cast<float4*>(d_sbas + (size_t)slot * 8);
    p[0] = make_float4(bs[0], bs[1], bs[2], bs[3]);
    p[1] = make_float4(bs[4], bs[5], bs[6], bs[7]);
}

// ---------------- edge-ordered gather + fused BN/relu -------------------------
// xe[slot][0..CIN) = relu(bn(xin[esrc[slot]]))   (one thread per edge-float4)
template <int CIN>
__global__ void k_gather(const float* __restrict__ xin,
                         const float* __restrict__ stat,
                         const float* __restrict__ g, const float* __restrict__ b) {
    constexpr int CH = CIN / 4;            // float4 chunks per row
    __shared__ float sc[CIN], sh[CIN];
    if (threadIdx.x < CIN) {
        float mean = stat[threadIdx.x] * (1.f / NN);
        float var = stat[CIN + threadIdx.x] * (1.f / NN) - mean * mean;
        float s = rsqrtf(var + EPSB) * g[threadIdx.x];
        sc[threadIdx.x] = s;
        sh[threadIdx.x] = b[threadIdx.x] - mean * s;
    }
    __syncthreads();
    int t = blockIdx.x * blockDim.x + threadIdx.x;
    if (t >= EE * CH) return;
    int slot = t / CH;
    int q = t % CH;
    int sn = d_esrc[slot];
    float4 v = reinterpret_cast<const float4*>(xin + (size_t)sn * CIN)[q];
    v.x = fmaxf(v.x * sc[4 * q + 0] + sh[4 * q + 0], 0.f);
    v.y = fmaxf(v.y * sc[4 * q + 1] + sh[4 * q + 1], 0.f);
    v.z = fmaxf(v.z * sc[4 * q + 2] + sh[4 * q + 2], 0.f);
    v.w = fmaxf(v.w * sc[4 * q + 3] + sh[4 * q + 3], 0.f);
    reinterpret_cast<float4*>(d_xe + (size_t)slot * CIN)[q] = v;
}

// ---------------- fused SplineConv: streaming outer-product + node GEMM -------
// For CIN>1: xin is EDGE-ORDERED (d_xe) — phase-1 is pure sequential streaming,
// no dependent loads. For CIN==1: xin is node-ordered raw x, gathered via esrc.
// Block: 256 threads = 32 sub-warps of 8 lanes (lane = kernel index s).
template <int CIN, int COUT>
__global__ __launch_bounds__(256) void k_conv(const float* __restrict__ xin,
                                              float* __restrict__ xout,
                                              const float* __restrict__ W,
                                              float* __restrict__ ostat) {
    constexpr int K = 8 * CIN;
    constexpr int KP = K + 4;          // rows stay 16B-aligned (KP % 4 == 0)
    constexpr int DB = 32;             // dsts per block
    constexpr int DS = 256 / COUT;
    constexpr int OPT = DB / DS;
    constexpr int Q2 = (CIN >= 4) ? CIN / 4 : 1;   // ulonglong2 loads per row
    constexpr int P2 = (CIN >= 2) ? CIN / 2 : 1;   // packed T accumulators
    __shared__ float Tsh[DB * K];
    __shared__ float Wt[COUT * KP];    // transposed: Wt[c][k]
    __shared__ float ssum[32], ssq[32];
    int tid = threadIdx.x;
    for (int i = tid; i < K * COUT; i += 256) {
        int k = i / COUT, c = i % COUT;
        Wt[c * KP + k] = W[i];
    }
    if (tid < 32) { ssum[tid] = 0.f; ssq[tid] = 0.f; }
    __syncthreads();

    int sub = tid >> 3;
    int s = tid & 7;
    int d = blockIdx.x * DB + sub;
    float invdeg = 0.f;

    if constexpr (CIN == 1) {
        float T0 = 0.f;
        if (d < NN) {
            int st = csr_off(d), en = csr_end(d);
            int j = st;
            for (; j + 1 < en; j += 2) {
                int sn0 = d_esrc[j], sn1 = d_esrc[j + 1];
                float b0 = d_sbas[(size_t)j * 8 + s];
                float b1 = d_sbas[(size_t)(j + 1) * 8 + s];
                float v0 = xin[sn0], v1 = xin[sn1];
                T0 += b0 * v0 + b1 * v1;
            }
            if (j < en) {
                T0 += d_sbas[(size_t)j * 8 + s] * xin[d_esrc[j]];
            }
            invdeg = 1.f / fmaxf((float)(en - st), 1.f);
        }
        Tsh[sub * K + s] = T0 * invdeg;
    } else {
        ull Tp[P2];
#pragma unroll
        for (int i = 0; i < P2; i++) Tp[i] = 0ull;
        if (d < NN) {
            int st = csr_off(d), en = csr_end(d);
            int j = st;
            // ---- pure streaming: addresses depend only on j ----
            for (; j + 1 < en; j += 2) {
                float b0 = d_sbas[(size_t)j * 8 + s];
                float b1 = d_sbas[(size_t)(j + 1) * 8 + s];
                const ulonglong2* x0 = reinterpret_cast<const ulonglong2*>(xin + (size_t)j * CIN);
                const ulonglong2* x1 = reinterpret_cast<const ulonglong2*>(xin + (size_t)(j + 1) * CIN);
                ulonglong2 v0[Q2], v1[Q2];
#pragma unroll
                for (int q = 0; q < Q2; q++) v0[q] = x0[q];
#pragma unroll
                for (int q = 0; q < Q2; q++) v1[q] = x1[q];
                ull bb0 = pack2(b0, b0);
                ull bb1 = pack2(b1, b1);
#pragma unroll
                for (int q = 0; q < Q2; q++) {
                    Tp[2 * q + 0] = ffma2(bb0, v0[q].x, Tp[2 * q + 0]);
                    Tp[2 * q + 1] = ffma2(bb0, v0[q].y, Tp[2 * q + 1]);
                }
#pragma unroll
                for (int q = 0; q < Q2; q++) {
                    Tp[2 * q + 0] = ffma2(bb1, v1[q].x, Tp[2 * q + 0]);
                    Tp[2 * q + 1] = ffma2(bb1, v1[q].y, Tp[2 * q + 1]);
                }
            }
            if (j < en) {
                float b0 = d_sbas[(size_t)j * 8 + s];
                const ulonglong2* x0 = reinterpret_cast<const ulonglong2*>(xin + (size_t)j * CIN);
                ull bb0 = pack2(b0, b0);
#pragma unroll
                for (int q = 0; q < Q2; q++) {
                    ulonglong2 v = x0[q];
                    Tp[2 * q + 0] = ffma2(bb0, v.x, Tp[2 * q + 0]);
                    Tp[2 * q + 1] = ffma2(bb0, v.y, Tp[2 * q + 1]);
                }
            }
            invdeg = 1.f / fmaxf((float)(en - st), 1.f);   // mean folded into T
        }
        ull iv2 = pack2(invdeg, invdeg);
#pragma unroll
        for (int i = 0; i < P2; i++)
            *reinterpret_cast<ull*>(&Tsh[sub * K + s * CIN + 2 * i]) = fmul2(Tp[i], iv2);
    }
    __syncthreads();

    // ---- GEMM phase (packed over k; horizontal add at end) ----
    int c = tid % COUT;
    int dl = tid / COUT;
    ull acc2a[OPT], acc2b[OPT];        // two chains per output for ILP
#pragma unroll
    for (int p = 0; p < OPT; p++) { acc2a[p] = 0ull; acc2b[p] = 0ull; }
#pragma unroll
    for (int k = 0; k < K; k += 4) {
        ulonglong2 w2 = *reinterpret_cast<const ulonglong2*>(&Wt[c * KP + k]);
#pragma unroll
        for (int p = 0; p < OPT; p++) {
            ulonglong2 t2 = *reinterpret_cast<const ulonglong2*>(&Tsh[(dl + p * DS) * K + k]);
            acc2a[p] = ffma2(w2.x, t2.x, acc2a[p]);
            acc2b[p] = ffma2(w2.y, t2.y, acc2b[p]);
        }
    }
    float ps = 0.f, pq = 0.f;
#pragma unroll
    for (int p = 0; p < OPT; p++) {
        int dd = blockIdx.x * DB + dl + p * DS;
        if (dd < NN) {
            ull t = fadd2(acc2a[p], acc2b[p]);
            float lo, hi;
            unpack2(t, lo, hi);
            float acc = lo + hi;
            xout[(size_t)dd * COUT + c] = acc;
            ps += acc; pq += acc * acc;
        }
    }
    atomicAdd(&ssum[c], ps);
    atomicAdd(&ssq[c], pq);
    __syncthreads();
    if (tid < COUT) {
        atomicAdd(&ostat[tid], ssum[tid]);
        atomicAdd(&ostat[COUT + tid], ssq[tid]);
    }
}

// ---------------- pooling-buffer zero (replaces 7 memsets) --------------------
__global__ void k_zero() {
    int i = blockIdx.x * blockDim.x + threadIdx.x;
    int T = gridDim.x * blockDim.x;
    int* adj4 = reinterpret_cast<int*>(d_adj);
    for (int p = i; p < (MM * MM) / 4; p += T) adj4[p] = 0;
    if (i < MM * 32) d_xp[i] = 0.f;
    if (i < MM * 3) d_pp[i] = 0.f;
    if (i < MM) d_cnt[i] = 0;
    if (i < BB * GRD * 32) d_xg[i] = 0.f;
    if (i == 0) { d_maxv = 0; d_nm = 0; }
}

// ---------------- voxel pooling (BN5+relu fused on read) ----------------------
__global__ void k_cluster(const float* __restrict__ pos, const int* __restrict__ batch,
                          const float* __restrict__ xin,
                          const float* __restrict__ pstat,
                          const float* __restrict__ g5, const float* __restrict__ b5) {
    __shared__ float sc[32], sh[32];
    if (threadIdx.x < 32) {
        float mean = pstat[threadIdx.x] * (1.f / NN);
        float var = pstat[32 + threadIdx.x] * (1.f / NN) - mean * mean;
        float s = rsqrtf(var + EPSB) * g5[threadIdx.x];
        sc[threadIdx.x] = s;
        sh[threadIdx.x] = b5[threadIdx.x] - mean * s;
    }
    __syncthreads();
    int n = blockIdx.x * blockDim.x + threadIdx.x;
    if (n >= NN) return;
    float p0 = pos[3 * n + 0], p1 = pos[3 * n + 1], p2 = pos[3 * n + 2];
    int cx = min(max((int)floorf(p0 / 16.0f), 0), NX_ - 1);
    int cy = min(max((int)floorf(p1 / 12.0f), 0), NY_ - 1);
    int cl = batch[n] * NCC + cy * NX_ + cx;
    d_clu[n] = cl;
    atomicAdd(&d_cnt[cl], 1);
    atomicAdd(&d_pp[cl * 3 + 0], p0);
    atomicAdd(&d_pp[cl * 3 + 1], p1);
    atomicAdd(&d_pp[cl * 3 + 2], p2);
    const float4* xr = reinterpret_cast<const float4*>(xin + (size_t)n * 32);
#pragma unroll
    for (int i = 0; i < 8; i++) {
        float4 v = xr[i];
        atomicMaxFloatPos(&d_xp[cl * 32 + 4 * i + 0], fmaxf(v.x * sc[4 * i + 0] + sh[4 * i + 0], 0.f));
        atomicMaxFloatPos(&d_xp[cl * 32 + 4 * i + 1], fmaxf(v.y * sc[4 * i + 1] + sh[4 * i + 1], 0.f));
        atomicMaxFloatPos(&d_xp[cl * 32 + 4 * i + 2], fmaxf(v.z * sc[4 * i + 2] + sh[4 * i + 2], 0.f));
        atomicMaxFloatPos(&d_xp[cl * 32 + 4 * i + 3], fmaxf(v.w * sc[4 * i + 3] + sh[4 * i + 3], 0.f));
    }
}

// ---------------- adjacency + pooled-position finalize (merged) ---------------
__global__ void k_adjpp(const int* __restrict__ src, const int* __restrict__ dst) {
    int e = blockIdx.x * blockDim.x + threadIdx.x;
    if (e < MM) {
        float c = fmaxf((float)d_cnt[e], 1.f);
        d_pp[e * 3 + 0] /= c;
        d_pp[e * 3 + 1] /= c;
        d_pp[e * 3 + 2] /= c;
        if (d_cnt[e] > 0) atomicAdd(&d_nm, 1);
    }
    if (e >= EE) return;
    int a = d_clu[src[e]], b = d_clu[dst[e]];
    if (a != b) d_adj[a * MM + b] = 1;
}

__global__ void k_maxv() {
    const int T = gridDim.x * blockDim.x;
    int t = blockIdx.x * blockDim.x + threadIdx.x;
    float mx = 0.f;
    for (int p = t; p < MM * MM; p += T) {
        if (d_adj[p]) {
            int r = p / MM, c = p % MM;
            mx = fmaxf(mx, fabsf(d_pp[c * 3 + 0] - d_pp[r * 3 + 0]));
            mx = fmaxf(mx, fabsf(d_pp[c * 3 + 1] - d_pp[r * 3 + 1]));
            mx = fmaxf(mx, fabsf(d_pp[c * 3 + 2] - d_pp[r * 3 + 2]));
        }
    }
    __shared__ float red[256];
    red[threadIdx.x] = mx;
    __syncthreads();
    for (int o = 128; o > 0; o >>= 1) {
        if (threadIdx.x < o) red[threadIdx.x] = fmaxf(red[threadIdx.x], red[threadIdx.x + o]);
        __syncthreads();
    }
    if (threadIdx.x == 0) atomicMax(&d_maxv, __float_as_int(red[0]));
}

// ---------------- pooled conv: per-node projections z = x . W[s] --------------
__global__ void k_pz(const float* __restrict__ xin, const float* __restrict__ W) {
    int t = blockIdx.x * blockDim.x + threadIdx.x;
    if (t >= MM * 8 * 32) return;
    int co = t & 31;
    int s = (t >> 5) & 7;
    int r = t >> 8;
    float acc = 0.f;
    const float* xr = &xin[r * 32];
    const float* wp = &W[s * 32 * 32 + co];
#pragma unroll
    for (int ci = 0; ci < 32; ci++) acc += xr[ci] * wp[ci * 32];
    d_pz[t] = acc;
}

// ---------------- pooled conv: per-dst aggregation ---------------------------
__global__ void k_pconv(float* __restrict__ out) {
    int c = blockIdx.x;
    int lane = threadIdx.x & 31;
    int w = threadIdx.x >> 5;  // 8 warps
    int g = c / NCC;
    int base = g * NCC;
    float inv = 0.5f / fmaxf(__int_as_float(d_maxv), 1e-9f);
    float pc0 = d_pp[c * 3 + 0], pc1 = d_pp[c * 3 + 1], pc2 = d_pp[c * 3 + 2];
    float acc = 0.f;
    int cnt = 0;
    for (int r = base + w; r < base + NCC; r += 8) {
        if (r == c || !d_adj[r * MM + c]) continue;
        cnt++;
        float bs[8];
        basis8((pc0 - d_pp[r * 3 + 0]) * inv + 0.5f,
               (pc1 - d_pp[r * 3 + 1]) * inv + 0.5f,
               (pc2 - d_pp[r * 3 + 2]) * inv + 0.5f, bs);
        const float* z = &d_pz[r * 256];
#pragma unroll
        for (int s = 0; s < 8; s++) acc += bs[s] * z[s * 32 + lane];
    }
    __shared__ float sa[8][32];
    __shared__ int scn[8];
    sa[w][lane] = acc;
    if (lane == 0) scn[w] = cnt;
    __syncthreads();
    if (w == 0) {
        float a = 0.f;
        int k = 0;
#pragma unroll
        for (int j = 0; j < 8; j++) { a += sa[j][lane]; k += scn[j]; }
        out[c * 32 + lane] = a / fmaxf((float)k, 1.f);
    }
}

// ---------------- pooled (masked) BN stats + finalize ------------------------
__global__ void k_pstats(const float* __restrict__ x) {
    int tid = threadIdx.x;  // one block, 1024 threads
    const int c = tid & 31;
    float sum = 0.f, sq = 0.f;
    for (int i = tid; i < MM * 32; i += 1024) {
        if (d_cnt[i >> 5] > 0) {
            float v = x[i];
            sum += v; sq += v * v;
        }
    }
    __shared__ float ss[32], s2[32];
    if (tid < 32) { ss[tid] = 0.f; s2[tid] = 0.f; }
    __syncthreads();
    atomicAdd(&ss[c], sum);
    atomicAdd(&s2[c], sq);
    __syncthreads();
    if (tid < 32) { d_pstats[tid] = ss[tid]; d_pstats[32 + tid] = s2[tid]; }
}

__global__ void k_pbn(const float* __restrict__ x, const float* __restrict__ g,
                      const float* __restrict__ b, float* __restrict__ out) {
    int i = blockIdx.x * blockDim.x + threadIdx.x;
    if (i >= MM * 32) return;
    int c = i & 31;
    float cntf = fmaxf((float)d_nm, 1.f);
    float mean = d_pstats[c] / cntf;
    float var = d_pstats[32 + c] / cntf - mean * mean;
    float v = (x[i] - mean) * rsqrtf(var + EPSB) * g[c] + b[c];
    if (d_cnt[i >> 5] <= 0) v = 0.f;
    out[i] = fmaxf(v, 0.f);
}

// ---------------- MaxPoolingX + FC -------------------------------------------
__global__ void k_poolX(const float* __restrict__ x) {
    int i = blockIdx.x * blockDim.x + threadIdx.x;
    if (i >= MM * 32) return;
    int m = i >> 5, ch = i & 31;
    if (d_cnt[m] <= 0) return;
    int g = m / NCC;
    int gx = min(max((int)floorf(d_pp[m * 3 + 0] / 30.0f), 0), 3);
    int gy = min(max((int)floorf(d_pp[m * 3 + 1] / 25.0f), 0), 3);
    int seg = g * GRD + gy * 4 + gx;
    atomicMaxFloatPos(&d_xg[seg * 32 + ch], x[i]);
}

__global__ void k_fc(const float* __restrict__ fcw, float* __restrict__ out) {
    int b = blockIdx.x;            // BB blocks
    int o = threadIdx.x >> 5;      // 2 warps
    int lane = threadIdx.x & 31;
    float s = 0.f;
    for (int j = lane; j < GRD * 32; j += 32)
        s += d_xg[b * GRD * 32 + j] * fcw[o * GRD * 32 + j];
#pragma unroll
    for (int off = 16; off; off >>= 1) s += __shfl_down_sync(0xffffffff, s, off);
    if (lane == 0) out[b * NOUTC + o] = s;
}

// ---------------- host orchestration -----------------------------------------
extern "C" void kernel_launch(void* const* d_in, const int* in_sizes, int n_in,
                              void* d_out, int out_size) {
    const float* x   = (const float*)d_in[0];
    const float* pos = (const float*)d_in[1];
    const float* ea  = (const float*)d_in[2];
    const float* w[7];
    const float* gm[7];
    const float* bt[7];
    for (int i = 0; i < 7; i++) {
        w[i]  = (const float*)d_in[3 + i];
        gm[i] = (const float*)d_in[10 + i];
        bt[i] = (const float*)d_in[17 + i];
    }
    const float* fcw = (const float*)d_in[24];
    const int* ei    = (const int*)d_in[25];
    const int* batch = (const int*)d_in[26];
    const int* src = ei;
    const int* dst = ei + EE;
    float* out = (float*)d_out;

    void *pdeg, *pxA, *pxe, *pstatsAll, *pxp, *pxu;
    cudaGetSymbolAddress(&pdeg, d_deg);
    cudaGetSymbolAddress(&pxA, d_xA);
    cudaGetSymbolAddress(&pxe, d_xe);
    cudaGetSymbolAddress(&pstatsAll, d_statsAll);
    cudaGetSymbolAddress(&pxp, d_xp);
    cudaGetSymbolAddress(&pxu, d_xu);
    float* fxA = (float*)pxA;
    float* fxe = (float*)pxe;
    float* st  = (float*)pstatsAll;   // st + 64*i = stats of conv i

    const int TB = 256;
    const int EG = (EE + TB - 1) / TB;
    const int NG = (NN + TB - 1) / TB;
    const int SB = (NN + 255) / 256;
    const int DG = (NN + 31) / 32;
    const int G8  = (EE * 2 + TB - 1) / TB;   // gather grid, CIN=8
    const int G16 = (EE * 4 + TB - 1) / TB;   // gather grid, CIN=16

    // ---- CSR build ----
    cudaMemsetAsync(pdeg, 0, (size_t)NN * 4, 0);
    k_deg<<<EG, TB>>>(dst);
    k_scanA<<<SB, 256>>>();
    k_scanB<<<1, 1024>>>(SB);
    k_fill<<<EG, TB>>>(src, dst, ea);

    // ---- conv1: 1 -> 8 (direct gather; raw x, no BN) ----
    k_conv<1,  8 ><<<DG, 256>>>(x, fxA, w[0], st + 0);

    // ---- conv2: 8 -> 16 ----
    k_gather<8 ><<<G8,  TB>>>(fxA, st + 0,   gm[0], bt[0]);
    k_conv<8,  16><<<DG, 256>>>(fxe, fxA, w[1], st + 64);

    // ---- conv3: 16 -> 16 ----
    k_gather<16><<<G16, TB>>>(fxA, st + 64,  gm[1], bt[1]);
    k_conv<16, 16><<<DG, 256>>>(fxe, fxA, w[2], st + 128);

    // ---- conv4: 16 -> 16 ----
    k_gather<16><<<G16, TB>>>(fxA, st + 128, gm[2], bt[2]);
    k_conv<16, 16><<<DG, 256>>>(fxe, fxA, w[3], st + 192);

    // ---- conv5: 16 -> 32 ----
    k_gather<16><<<G16, TB>>>(fxA, st + 192, gm[3], bt[3]);
    k_conv<16, 32><<<DG, 256>>>(fxe, fxA, w[4], st + 256);
    // BN5 + relu fused into k_cluster below

    // ---- MaxPooling (voxel grid) ----
    k_zero<<<232, 256>>>();
    k_cluster<<<NG, TB>>>(pos, batch, fxA, st + 256, gm[4], bt[4]);
    k_adjpp<<<EG, TB>>>(src, dst);
    k_maxv<<<592, TB>>>();

    // ---- conv6: 32 -> 32 (pooled) ----
    k_pz<<<(MM * 256 + TB - 1) / TB, TB>>>((const float*)pxp, w[5]);
    k_pconv<<<MM, 256>>>(d_xt);
    k_pstats<<<1, 1024>>>(d_xt);
    k_pbn<<<(MM * 32 + TB - 1) / TB, TB>>>(d_xt, gm[5], bt[5], (float*)pxu);

    // ---- conv7: 32 -> 32 (pooled) ----
    k_pz<<<(MM * 256 + TB - 1) / TB, TB>>>((const float*)pxu, w[6]);
    k_pconv<<<MM, 256>>>(d_xt);
    k_pstats<<<1, 1024>>>(d_xt);
    k_pbn<<<(MM * 32 + TB - 1) / TB, TB>>>(d_xt, gm[6], bt[6], (float*)pxu);

    // ---- MaxPoolingX + FC ----
    k_poolX<<<(MM * 32 + TB - 1) / TB, TB>>>((const float*)pxu);
    k_fc<<<BB, 64>>>(fcw, out);
}

// round 11
// speedup vs baseline: 1.0430x; 1.0430x over previous
#include <cuda_runtime.h>
#include <math.h>

#define NN   250000
#define EE   1000000
#define BB   25
#define NX_  8
#define NY_  9
#define NCC  72
#define MM   1800
#define GRD  16
#define NOUTC 2
#define EPSB 1e-5f

typedef unsigned long long ull;

// ---------------- f32x2 packed-math helpers (sm_10x) --------------------------
__device__ __forceinline__ ull pack2(float x, float y) {
    ull r; asm("mov.b64 %0, {%1, %2};" : "=l"(r) : "f"(x), "f"(y)); return r;
}
__device__ __forceinline__ void unpack2(ull v, float& x, float& y) {
    asm("mov.b64 {%0, %1}, %2;" : "=f"(x), "=f"(y) : "l"(v));
}
__device__ __forceinline__ ull ffma2(ull a, ull b, ull c) {
    ull d; asm("fma.rn.f32x2 %0, %1, %2, %3;" : "=l"(d) : "l"(a), "l"(b), "l"(c)); return d;
}
__device__ __forceinline__ ull fmul2(ull a, ull b) {
    ull d; asm("mul.rn.f32x2 %0, %1, %2;" : "=l"(d) : "l"(a), "l"(b)); return d;
}
__device__ __forceinline__ ull fadd2(ull a, ull b) {
    ull d; asm("add.rn.f32x2 %0, %1, %2;" : "=l"(d) : "l"(a), "l"(b)); return d;
}

// ---------------- scratch (device globals; no allocation allowed) -------------
__device__ float d_xA[NN * 32];              // ping
__device__ float d_xB[NN * 32];              // pong
__device__ int   d_deg[NN];
__device__ int   d_off[NN];                  // CSR offsets (block-partial; add pbase)
__device__ int   d_cur[NN];                  // fill cursors
__device__ int   d_part[1024];               // scan partials
__device__ int   d_pbase[1024];
__device__ int   d_esrc[EE];                 // CSR-ordered source node ids
__device__ __align__(16) float d_sbas[(size_t)EE * 8];  // CSR-ordered basis (32MB)
__device__ int   d_clu[NN];
__device__ float d_statsAll[5 * 64];         // per-conv [sum(C), sumsq(C)]
__device__ float d_xp[MM * 32];              // pooled features (max pooled)
__device__ float d_pp[MM * 3];               // pooled positions
__device__ int   d_cnt[MM];
__device__ unsigned char d_adj[MM * MM];
__device__ int   d_maxv;                     // float bits (non-negative)
__device__ int   d_nm;                       // number of non-empty cells
__device__ float d_pstats[64];               // pooled BN stats
__device__ float d_pz[MM * 8 * 32];          // pooled per-node projections
__device__ float d_xt[MM * 32];              // pooled conv raw output
__device__ float d_xu[MM * 32];              // pooled conv post-BN output
__device__ float d_xg[BB * GRD * 32];        // MaxPoolingX output

// ---------------- helpers ----------------------------------------------------
__device__ __forceinline__ int csr_off(int d) {
    return d_off[d] + d_pbase[d >> 8];
}
__device__ __forceinline__ int csr_end(int d) {
    return (d == NN - 1) ? EE : csr_off(d + 1);
}

__device__ __forceinline__ void basis8(float p0, float p1, float p2, float* b) {
    p0 = fminf(fmaxf(p0, 0.f), 1.f);
    p1 = fminf(fmaxf(p1, 0.f), 1.f);
    p2 = fminf(fmaxf(p2, 0.f), 1.f);
    float q0 = 1.f - p0, q1 = 1.f - p1, q2 = 1.f - p2;
    b[0] = q0 * q1 * q2; b[1] = p0 * q1 * q2;
    b[2] = q0 * p1 * q2; b[3] = p0 * p1 * q2;
    b[4] = q0 * q1 * p2; b[5] = p0 * q1 * p2;
    b[6] = q0 * p1 * p2; b[7] = p0 * p1 * p2;
}

__device__ __forceinline__ void atomicMaxFloatPos(float* addr, float v) {
    atomicMax(reinterpret_cast<int*>(addr), __float_as_int(v));
}

// ---------------- degree + CSR build -----------------------------------------
__global__ void k_deg(const int* __restrict__ dst) {
    int e = blockIdx.x * blockDim.x + threadIdx.x;
    if (e < EE) atomicAdd(&d_deg[dst[e]], 1);
}

__global__ void k_scanA() {  // 256 threads/block; also zeroes d_cur
    __shared__ int sm[256];
    int i = blockIdx.x * 256 + threadIdx.x;
    int v = (i < NN) ? d_deg[i] : 0;
    if (i < NN) d_cur[i] = 0;
    sm[threadIdx.x] = v;
    __syncthreads();
    for (int off = 1; off < 256; off <<= 1) {
        int t = (threadIdx.x >= off) ? sm[threadIdx.x - off] : 0;
        __syncthreads();
        sm[threadIdx.x] += t;
        __syncthreads();
    }
    if (i < NN) d_off[i] = sm[threadIdx.x] - v;  // exclusive within block
    if (threadIdx.x == 255) d_part[blockIdx.x] = sm[255];
}

__global__ void k_scanB(int nparts) {  // 1 block, 1024 threads
    __shared__ int sm[1024];
    int v = (threadIdx.x < nparts) ? d_part[threadIdx.x] : 0;
    sm[threadIdx.x] = v;
    __syncthreads();
    for (int off = 1; off < 1024; off <<= 1) {
        int t = (threadIdx.x >= off) ? sm[threadIdx.x - off] : 0;
        __syncthreads();
        sm[threadIdx.x] += t;
        __syncthreads();
    }
    if (threadIdx.x < nparts) d_pbase[threadIdx.x] = sm[threadIdx.x] - v;
}

__global__ void k_fill(const int* __restrict__ src, const int* __restrict__ dst,
                       const float* __restrict__ ea) {
    int e = blockIdx.x * blockDim.x + threadIdx.x;
    if (e < 5 * 64) d_statsAll[e] = 0.f;     // zero all conv BN stats
    if (e >= EE) return;
    int d = dst[e];
    int slot = csr_off(d) + atomicAdd(&d_cur[d], 1);
    d_esrc[slot] = src[e];
    float bs[8];
    basis8(ea[3 * e + 0], ea[3 * e + 1], ea[3 * e + 2], bs);
    float4* p = reinterpret_cast<float4*>(d_sbas + (size_t)slot * 8);
    p[0] = make_float4(bs[0], bs[1], bs[2], bs[3]);
    p[1] = make_float4(bs[4], bs[5], bs[6], bs[7]);
}

// ---------------- fused SplineConv: gather outer-product + node GEMM ----------
// out[d] = ((1/deg) * sum_e b_e (x) x_src(e)) . W_flat[8*CIN, COUT]
// Block: 256 threads = 32 sub-warps of 8 lanes (lane = kernel index s).
// __launch_bounds__(256, 4): cap regs ~64 so >=4 blocks/SM hide L2 latency.
template <int CIN, int COUT>
__global__ __launch_bounds__(256, 4) void k_conv(const float* __restrict__ xin,
                                                 float* __restrict__ xout,
                                                 const float* __restrict__ W,
                                                 float* __restrict__ ostat) {
    constexpr int K = 8 * CIN;
    constexpr int KP = K + 4;          // rows stay 16B-aligned (KP % 4 == 0)
    constexpr int DB = 32;             // dsts per block
    constexpr int DS = 256 / COUT;
    constexpr int OPT = DB / DS;
    constexpr int Q2 = (CIN >= 4) ? CIN / 4 : 1;   // ulonglong2 loads per x row
    constexpr int P2 = (CIN >= 2) ? CIN / 2 : 1;   // packed T accumulators
    __shared__ float Tsh[DB * K];
    __shared__ float Wt[COUT * KP];    // transposed: Wt[c][k]
    __shared__ float ssum[32], ssq[32];
    int tid = threadIdx.x;
    for (int i = tid; i < K * COUT; i += 256) {
        int k = i / COUT, c = i % COUT;
        Wt[c * KP + k] = W[i];
    }
    if (tid < 32) { ssum[tid] = 0.f; ssq[tid] = 0.f; }
    __syncthreads();

    int sub = tid >> 3;
    int s = tid & 7;
    int d = blockIdx.x * DB + sub;
    float invdeg = 0.f;

    if constexpr (CIN == 1) {
        float T0 = 0.f;
        if (d < NN) {
            int st = csr_off(d), en = csr_end(d);
            int j = st;
            for (; j + 1 < en; j += 2) {
                int sn0 = d_esrc[j], sn1 = d_esrc[j + 1];
                float b0 = d_sbas[(size_t)j * 8 + s];
                float b1 = d_sbas[(size_t)(j + 1) * 8 + s];
                float v0 = xin[sn0], v1 = xin[sn1];
                T0 += b0 * v0 + b1 * v1;
            }
            if (j < en) {
                T0 += d_sbas[(size_t)j * 8 + s] * xin[d_esrc[j]];
            }
            invdeg = 1.f / fmaxf((float)(en - st), 1.f);
        }
        Tsh[sub * K + s] = T0 * invdeg;
    } else {
        ull Tp[P2];
#pragma unroll
        for (int i = 0; i < P2; i++) Tp[i] = 0ull;
        if (d < NN) {
            int st = csr_off(d), en = csr_end(d);
            int j = st;
            // ---- 2-edge pipeline; v1 consumed right after v0 to limit regs ----
            for (; j + 1 < en; j += 2) {
                int sn0 = d_esrc[j], sn1 = d_esrc[j + 1];
                float b0 = d_sbas[(size_t)j * 8 + s];
                float b1 = d_sbas[(size_t)(j + 1) * 8 + s];
                const ulonglong2* x0 = reinterpret_cast<const ulonglong2*>(xin + (size_t)sn0 * CIN);
                const ulonglong2* x1 = reinterpret_cast<const ulonglong2*>(xin + (size_t)sn1 * CIN);
                ull bb0 = pack2(b0, b0);
                ull bb1 = pack2(b1, b1);
#pragma unroll
                for (int q = 0; q < Q2; q++) {
                    ulonglong2 v0 = x0[q];
                    Tp[2 * q + 0] = ffma2(bb0, v0.x, Tp[2 * q + 0]);
                    Tp[2 * q + 1] = ffma2(bb0, v0.y, Tp[2 * q + 1]);
                }
#pragma unroll
                for (int q = 0; q < Q2; q++) {
                    ulonglong2 v1 = x1[q];
                    Tp[2 * q + 0] = ffma2(bb1, v1.x, Tp[2 * q + 0]);
                    Tp[2 * q + 1] = ffma2(bb1, v1.y, Tp[2 * q + 1]);
                }
            }
            if (j < en) {
                int sn0 = d_esrc[j];
                float b0 = d_sbas[(size_t)j * 8 + s];
                const ulonglong2* x0 = reinterpret_cast<const ulonglong2*>(xin + (size_t)sn0 * CIN);
                ull bb0 = pack2(b0, b0);
#pragma unroll
                for (int q = 0; q < Q2; q++) {
                    ulonglong2 v = x0[q];
                    Tp[2 * q + 0] = ffma2(bb0, v.x, Tp[2 * q + 0]);
                    Tp[2 * q + 1] = ffma2(bb0, v.y, Tp[2 * q + 1]);
                }
            }
            invdeg = 1.f / fmaxf((float)(en - st), 1.f);   // mean folded into T
        }
        ull iv2 = pack2(invdeg, invdeg);
#pragma unroll
        for (int i = 0; i < P2; i++)
            *reinterpret_cast<ull*>(&Tsh[sub * K + s * CIN + 2 * i]) = fmul2(Tp[i], iv2);
    }
    __syncthreads();

    // ---- GEMM phase (packed over k; horizontal add at end) ----
    int c = tid % COUT;
    int dl = tid / COUT;
    ull acc2a[OPT], acc2b[OPT];        // two chains per output for ILP
#pragma unroll
    for (int p = 0; p < OPT; p++) { acc2a[p] = 0ull; acc2b[p] = 0ull; }
#pragma unroll
    for (int k = 0; k < K; k += 4) {
        ulonglong2 w2 = *reinterpret_cast<const ulonglong2*>(&Wt[c * KP + k]);
#pragma unroll
        for (int p = 0; p < OPT; p++) {
            ulonglong2 t2 = *reinterpret_cast<const ulonglong2*>(&Tsh[(dl + p * DS) * K + k]);
            acc2a[p] = ffma2(w2.x, t2.x, acc2a[p]);
            acc2b[p] = ffma2(w2.y, t2.y, acc2b[p]);
        }
    }
    float ps = 0.f, pq = 0.f;
#pragma unroll
    for (int p = 0; p < OPT; p++) {
        int dd = blockIdx.x * DB + dl + p * DS;
        if (dd < NN) {
            ull t = fadd2(acc2a[p], acc2b[p]);
            float lo, hi;
            unpack2(t, lo, hi);
            float acc = lo + hi;
            xout[(size_t)dd * COUT + c] = acc;
            ps += acc; pq += acc * acc;
        }
    }
    atomicAdd(&ssum[c], ps);
    atomicAdd(&ssq[c], pq);
    __syncthreads();
    if (tid < COUT) {
        atomicAdd(&ostat[tid], ssum[tid]);
        atomicAdd(&ostat[COUT + tid], ssq[tid]);
    }
}

// ---------------- BN apply + relu (in place, vectorized, consts in prologue) --
template <int C>
__global__ void k_bnapply(float* __restrict__ xio, const float* __restrict__ stat,
                          const float* __restrict__ g, const float* __restrict__ b) {
    __shared__ float sc[C], sh[C];
    if (threadIdx.x < C) {
        float mean = stat[threadIdx.x] * (1.f / NN);
        float var = stat[C + threadIdx.x] * (1.f / NN) - mean * mean;
        float s = rsqrtf(var + EPSB) * g[threadIdx.x];
        sc[threadIdx.x] = s;
        sh[threadIdx.x] = b[threadIdx.x] - mean * s;
    }
    __syncthreads();
    int i = blockIdx.x * blockDim.x + threadIdx.x;   // float4 index
    if (i >= NN * C / 4) return;
    int cb = (i % (C / 4)) * 4;
    float4 v = reinterpret_cast<float4*>(xio)[i];
    v.x = fmaxf(v.x * sc[cb + 0] + sh[cb + 0], 0.f);
    v.y = fmaxf(v.y * sc[cb + 1] + sh[cb + 1], 0.f);
    v.z = fmaxf(v.z * sc[cb + 2] + sh[cb + 2], 0.f);
    v.w = fmaxf(v.w * sc[cb + 3] + sh[cb + 3], 0.f);
    reinterpret_cast<float4*>(xio)[i] = v;
}

// ---------------- pooling-buffer zero (replaces 7 memsets) --------------------
__global__ void k_zero() {
    int i = blockIdx.x * blockDim.x + threadIdx.x;
    int T = gridDim.x * blockDim.x;
    int* adj4 = reinterpret_cast<int*>(d_adj);
    for (int p = i; p < (MM * MM) / 4; p += T) adj4[p] = 0;
    if (i < MM * 32) d_xp[i] = 0.f;
    if (i < MM * 3) d_pp[i] = 0.f;
    if (i < MM) d_cnt[i] = 0;
    if (i < BB * GRD * 32) d_xg[i] = 0.f;
    if (i == 0) { d_maxv = 0; d_nm = 0; }
}

// ---------------- voxel pooling (BN5+relu fused on read) ----------------------
__global__ void k_cluster(const float* __restrict__ pos, const int* __restrict__ batch,
                          const float* __restrict__ xin,
                          const float* __restrict__ pstat,
                          const float* __restrict__ g5, const float* __restrict__ b5) {
    __shared__ float sc[32], sh[32];
    if (threadIdx.x < 32) {
        float mean = pstat[threadIdx.x] * (1.f / NN);
        float var = pstat[32 + threadIdx.x] * (1.f / NN) - mean * mean;
        float s = rsqrtf(var + EPSB) * g5[threadIdx.x];
        sc[threadIdx.x] = s;
        sh[threadIdx.x] = b5[threadIdx.x] - mean * s;
    }
    __syncthreads();
    int n = blockIdx.x * blockDim.x + threadIdx.x;
    if (n >= NN) return;
    float p0 = pos[3 * n + 0], p1 = pos[3 * n + 1], p2 = pos[3 * n + 2];
    int cx = min(max((int)floorf(p0 / 16.0f), 0), NX_ - 1);
    int cy = min(max((int)floorf(p1 / 12.0f), 0), NY_ - 1);
    int cl = batch[n] * NCC + cy * NX_ + cx;
    d_clu[n] = cl;
    atomicAdd(&d_cnt[cl], 1);
    atomicAdd(&d_pp[cl * 3 + 0], p0);
    atomicAdd(&d_pp[cl * 3 + 1], p1);
    atomicAdd(&d_pp[cl * 3 + 2], p2);
    const float4* xr = reinterpret_cast<const float4*>(xin + (size_t)n * 32);
#pragma unroll
    for (int i = 0; i < 8; i++) {
        float4 v = xr[i];
        atomicMaxFloatPos(&d_xp[cl * 32 + 4 * i + 0], fmaxf(v.x * sc[4 * i + 0] + sh[4 * i + 0], 0.f));
        atomicMaxFloatPos(&d_xp[cl * 32 + 4 * i + 1], fmaxf(v.y * sc[4 * i + 1] + sh[4 * i + 1], 0.f));
        atomicMaxFloatPos(&d_xp[cl * 32 + 4 * i + 2], fmaxf(v.z * sc[4 * i + 2] + sh[4 * i + 2], 0.f));
        atomicMaxFloatPos(&d_xp[cl * 32 + 4 * i + 3], fmaxf(v.w * sc[4 * i + 3] + sh[4 * i + 3], 0.f));
    }
}

// ---------------- adjacency + pooled-position finalize (merged) ---------------
__global__ void k_adjpp(const int* __restrict__ src, const int* __restrict__ dst) {
    int e = blockIdx.x * blockDim.x + threadIdx.x;
    if (e < MM) {
        float c = fmaxf((float)d_cnt[e], 1.f);
        d_pp[e * 3 + 0] /= c;
        d_pp[e * 3 + 1] /= c;
        d_pp[e * 3 + 2] /= c;
        if (d_cnt[e] > 0) atomicAdd(&d_nm, 1);
    }
    if (e >= EE) return;
    int a = d_clu[src[e]], b = d_clu[dst[e]];
    if (a != b) d_adj[a * MM + b] = 1;
}

__global__ void k_maxv() {
    const int T = gridDim.x * blockDim.x;
    int t = blockIdx.x * blockDim.x + threadIdx.x;
    float mx = 0.f;
    for (int p = t; p < MM * MM; p += T) {
        if (d_adj[p]) {
            int r = p / MM, c = p % MM;
            mx = fmaxf(mx, fabsf(d_pp[c * 3 + 0] - d_pp[r * 3 + 0]));
            mx = fmaxf(mx, fabsf(d_pp[c * 3 + 1] - d_pp[r * 3 + 1]));
            mx = fmaxf(mx, fabsf(d_pp[c * 3 + 2] - d_pp[r * 3 + 2]));
        }
    }
    __shared__ float red[256];
    red[threadIdx.x] = mx;
    __syncthreads();
    for (int o = 128; o > 0; o >>= 1) {
        if (threadIdx.x < o) red[threadIdx.x] = fmaxf(red[threadIdx.x], red[threadIdx.x + o]);
        __syncthreads();
    }
    if (threadIdx.x == 0) atomicMax(&d_maxv, __float_as_int(red[0]));
}

// ---------------- pooled conv: per-node projections z = x . W[s] --------------
__global__ void k_pz(const float* __restrict__ xin, const float* __restrict__ W) {
    int t = blockIdx.x * blockDim.x + threadIdx.x;
    if (t >= MM * 8 * 32) return;
    int co = t & 31;
    int s = (t >> 5) & 7;
    int r = t >> 8;
    float acc = 0.f;
    const float* xr = &xin[r * 32];
    const float* wp = &W[s * 32 * 32 + co];
#pragma unroll
    for (int ci = 0; ci < 32; ci++) acc += xr[ci] * wp[ci * 32];
    d_pz[t] = acc;
}

// ---------------- pooled conv: per-dst aggregation ---------------------------
__global__ void k_pconv(float* __restrict__ out) {
    int c = blockIdx.x;
    int lane = threadIdx.x & 31;
    int w = threadIdx.x >> 5;  // 8 warps
    int g = c / NCC;
    int base = g * NCC;
    float inv = 0.5f / fmaxf(__int_as_float(d_maxv), 1e-9f);
    float pc0 = d_pp[c * 3 + 0], pc1 = d_pp[c * 3 + 1], pc2 = d_pp[c * 3 + 2];
    float acc = 0.f;
    int cnt = 0;
    for (int r = base + w; r < base + NCC; r += 8) {
        if (r == c || !d_adj[r * MM + c]) continue;
        cnt++;
        float bs[8];
        basis8((pc0 - d_pp[r * 3 + 0]) * inv + 0.5f,
               (pc1 - d_pp[r * 3 + 1]) * inv + 0.5f,
               (pc2 - d_pp[r * 3 + 2]) * inv + 0.5f, bs);
        const float* z = &d_pz[r * 256];
#pragma unroll
        for (int s = 0; s < 8; s++) acc += bs[s] * z[s * 32 + lane];
    }
    __shared__ float sa[8][32];
    __shared__ int scn[8];
    sa[w][lane] = acc;
    if (lane == 0) scn[w] = cnt;
    __syncthreads();
    if (w == 0) {
        float a = 0.f;
        int k = 0;
#pragma unroll
        for (int j = 0; j < 8; j++) { a += sa[j][lane]; k += scn[j]; }
        out[c * 32 + lane] = a / fmaxf((float)k, 1.f);
    }
}

// ---------------- pooled (masked) BN stats + finalize ------------------------
__global__ void k_pstats(const float* __restrict__ x) {
    int tid = threadIdx.x;  // one block, 1024 threads
    const int c = tid & 31;
    float sum = 0.f, sq = 0.f;
    for (int i = tid; i < MM * 32; i += 1024) {
        if (d_cnt[i >> 5] > 0) {
            float v = x[i];
            sum += v; sq += v * v;
        }
    }
    __shared__ float ss[32], s2[32];
    if (tid < 32) { ss[tid] = 0.f; s2[tid] = 0.f; }
    __syncthreads();
    atomicAdd(&ss[c], sum);
    atomicAdd(&s2[c], sq);
    __syncthreads();
    if (tid < 32) { d_pstats[tid] = ss[tid]; d_pstats[32 + tid] = s2[tid]; }
}

__global__ void k_pbn(const float* __restrict__ x, const float* __restrict__ g,
                      const float* __restrict__ b, float* __restrict__ out) {
    int i = blockIdx.x * blockDim.x + threadIdx.x;
    if (i >= MM * 32) return;
    int c = i & 31;
    float cntf = fmaxf((float)d_nm, 1.f);
    float mean = d_pstats[c] / cntf;
    float var = d_pstats[32 + c] / cntf - mean * mean;
    float v = (x[i] - mean) * rsqrtf(var + EPSB) * g[c] + b[c];
    if (d_cnt[i >> 5] <= 0) v = 0.f;
    out[i] = fmaxf(v, 0.f);
}

// ---------------- MaxPoolingX + FC -------------------------------------------
__global__ void k_poolX(const float* __restrict__ x) {
    int i = blockIdx.x * blockDim.x + threadIdx.x;
    if (i >= MM * 32) return;
    int m = i >> 5, ch = i & 31;
    if (d_cnt[m] <= 0) return;
    int g = m / NCC;
    int gx = min(max((int)floorf(d_pp[m * 3 + 0] / 30.0f), 0), 3);
    int gy = min(max((int)floorf(d_pp[m * 3 + 1] / 25.0f), 0), 3);
    int seg = g * GRD + gy * 4 + gx;
    atomicMaxFloatPos(&d_xg[seg * 32 + ch], x[i]);
}

__global__ void k_fc(const float* __restrict__ fcw, float* __restrict__ out) {
    int b = blockIdx.x;            // BB blocks
    int o = threadIdx.x >> 5;      // 2 warps
    int lane = threadIdx.x & 31;
    float s = 0.f;
    for (int j = lane; j < GRD * 32; j += 32)
        s += d_xg[b * GRD * 32 + j] * fcw[o * GRD * 32 + j];
#pragma unroll
    for (int off = 16; off; off >>= 1) s += __shfl_down_sync(0xffffffff, s, off);
    if (lane == 0) out[b * NOUTC + o] = s;
}

// ---------------- host orchestration -----------------------------------------
extern "C" void kernel_launch(void* const* d_in, const int* in_sizes, int n_in,
                              void* d_out, int out_size) {
    const float* x   = (const float*)d_in[0];
    const float* pos = (const float*)d_in[1];
    const float* ea  = (const float*)d_in[2];
    const float* w[7];
    const float* gm[7];
    const float* bt[7];
    for (int i = 0; i < 7; i++) {
        w[i]  = (const float*)d_in[3 + i];
        gm[i] = (const float*)d_in[10 + i];
        bt[i] = (const float*)d_in[17 + i];
    }
    const float* fcw = (const float*)d_in[24];
    const int* ei    = (const int*)d_in[25];
    const int* batch = (const int*)d_in[26];
    const int* src = ei;
    const int* dst = ei + EE;
    float* out = (float*)d_out;

    void *pdeg, *pxA, *pxB, *pstatsAll, *pxp, *pxu;
    cudaGetSymbolAddress(&pdeg, d_deg);
    cudaGetSymbolAddress(&pxA, d_xA);
    cudaGetSymbolAddress(&pxB, d_xB);
    cudaGetSymbolAddress(&pstatsAll, d_statsAll);
    cudaGetSymbolAddress(&pxp, d_xp);
    cudaGetSymbolAddress(&pxu, d_xu);
    float* fxA = (float*)pxA;
    float* fxB = (float*)pxB;
    float* st  = (float*)pstatsAll;   // st + 64*i = stats of conv i

    const int TB = 256;
    const int EG = (EE + TB - 1) / TB;
    const int NG = (NN + TB - 1) / TB;
    const int SB = (NN + 255) / 256;
    const int DG = (NN + 31) / 32;

    // ---- CSR build ----
    cudaMemsetAsync(pdeg, 0, (size_t)NN * 4, 0);
    k_deg<<<EG, TB>>>(dst);
    k_scanA<<<SB, 256>>>();
    k_scanB<<<1, 1024>>>(SB);
    k_fill<<<EG, TB>>>(src, dst, ea);

    // ---- conv1..conv5 (post-BN applied in-place between convs) ----
    k_conv<1,  8 ><<<DG, 256>>>(x,   fxA, w[0], st + 0);
    k_bnapply<8 ><<<(NN * 8 / 4 + TB - 1) / TB, TB>>>(fxA, st + 0, gm[0], bt[0]);
    k_conv<8,  16><<<DG, 256>>>(fxA, fxB, w[1], st + 64);
    k_bnapply<16><<<(NN * 16 / 4 + TB - 1) / TB, TB>>>(fxB, st + 64, gm[1], bt[1]);
    k_conv<16, 16><<<DG, 256>>>(fxB, fxA, w[2], st + 128);
    k_bnapply<16><<<(NN * 16 / 4 + TB - 1) / TB, TB>>>(fxA, st + 128, gm[2], bt[2]);
    k_conv<16, 16><<<DG, 256>>>(fxA, fxB, w[3], st + 192);
    k_bnapply<16><<<(NN * 16 / 4 + TB - 1) / TB, TB>>>(fxB, st + 192, gm[3], bt[3]);
    k_conv<16, 32><<<DG, 256>>>(fxB, fxA, w[4], st + 256);
    // BN5 + relu fused into k_cluster below

    // ---- MaxPooling (voxel grid) ----
    k_zero<<<232, 256>>>();
    k_cluster<<<NG, TB>>>(pos, batch, fxA, st + 256, gm[4], bt[4]);
    k_adjpp<<<EG, TB>>>(src, dst);
    k_maxv<<<592, TB>>>();

    // ---- conv6: 32 -> 32 (pooled) ----
    k_pz<<<(MM * 256 + TB - 1) / TB, TB>>>((const float*)pxp, w[5]);
    k_pconv<<<MM, 256>>>(d_xt);
    k_pstats<<<1, 1024>>>(d_xt);
    k_pbn<<<(MM * 32 + TB - 1) / TB, TB>>>(d_xt, gm[5], bt[5], (float*)pxu);

    // ---- conv7: 32 -> 32 (pooled) ----
    k_pz<<<(MM * 256 + TB - 1) / TB, TB>>>((const float*)pxu, w[6]);
    k_pconv<<<MM, 256>>>(d_xt);
    k_pstats<<<1, 1024>>>(d_xt);
    k_pbn<<<(MM * 32 + TB - 1) / TB, TB>>>(d_xt, gm[6], bt[6], (float*)pxu);

    // ---- MaxPoolingX + FC ----
    k_poolX<<<(MM * 32 + TB - 1) / TB, TB>>>((const float*)pxu);
    k_fc<<<BB, 64>>>(fcw, out);
}

// round 12
// speedup vs baseline: 1.0923x; 1.0472x over previous
#include <cuda_runtime.h>
#include <math.h>

#define NN   250000
#define EE   1000000
#define BB   25
#define NX_  8
#define NY_  9
#define NCC  72
#define MM   1800
#define GRD  16
#define NOUTC 2
#define EPSB 1e-5f

typedef unsigned long long ull;

// ---------------- f32x2 packed-math helpers (sm_10x) --------------------------
__device__ __forceinline__ ull pack2(float x, float y) {
    ull r; asm("mov.b64 %0, {%1, %2};" : "=l"(r) : "f"(x), "f"(y)); return r;
}
__device__ __forceinline__ void unpack2(ull v, float& x, float& y) {
    asm("mov.b64 {%0, %1}, %2;" : "=f"(x), "=f"(y) : "l"(v));
}
__device__ __forceinline__ ull ffma2(ull a, ull b, ull c) {
    ull d; asm("fma.rn.f32x2 %0, %1, %2, %3;" : "=l"(d) : "l"(a), "l"(b), "l"(c)); return d;
}
__device__ __forceinline__ ull fmul2(ull a, ull b) {
    ull d; asm("mul.rn.f32x2 %0, %1, %2;" : "=l"(d) : "l"(a), "l"(b)); return d;
}
__device__ __forceinline__ ull fadd2(ull a, ull b) {
    ull d; asm("add.rn.f32x2 %0, %1, %2;" : "=l"(d) : "l"(a), "l"(b)); return d;
}

// ---------------- scratch (device globals; no allocation allowed) -------------
// NOTE: device globals are zero-initialized at module load -> first call sees
// d_deg == 0 without a memset; k_scanA re-zeroes it for subsequent replays.
__device__ float d_xA[NN * 32];              // ping
__device__ float d_xB[NN * 32];              // pong
__device__ int   d_deg[NN];
__device__ int   d_off[NN];                  // CSR offsets (block-partial; add pbase)
__device__ int   d_cur[NN];                  // fill cursors
__device__ int   d_part[1024];               // scan partials
__device__ int   d_pbase[1024];
__device__ int   d_esrc[EE];                 // CSR-ordered source node ids
__device__ __align__(16) float d_sbas[(size_t)EE * 8];  // CSR-ordered basis (32MB)
__device__ int   d_clu[NN];
__device__ float d_statsAll[5 * 64];         // per-conv [sum(C), sumsq(C)]
__device__ float d_xp[MM * 32];              // pooled features (max pooled)
__device__ float d_pp[MM * 3];               // pooled positions
__device__ int   d_cnt[MM];
__device__ unsigned char d_adj[MM * MM];
__device__ int   d_maxv;                     // float bits (non-negative)
__device__ int   d_nm;                       // number of non-empty cells
__device__ float d_pstats[128];              // pooled BN stats (2 conv slots)
__device__ float d_pz[MM * 8 * 32];          // pooled per-node projections
__device__ float d_xt[MM * 32];              // pooled conv raw output
__device__ float d_xu[MM * 32];              // pooled conv post-BN output
__device__ float d_xg[BB * GRD * 32];        // MaxPoolingX output

// ---------------- helpers ----------------------------------------------------
__device__ __forceinline__ int csr_off(int d) {
    return d_off[d] + d_pbase[d >> 8];
}
__device__ __forceinline__ int csr_end(int d) {
    return (d == NN - 1) ? EE : csr_off(d + 1);
}

__device__ __forceinline__ void basis8(float p0, float p1, float p2, float* b) {
    p0 = fminf(fmaxf(p0, 0.f), 1.f);
    p1 = fminf(fmaxf(p1, 0.f), 1.f);
    p2 = fminf(fmaxf(p2, 0.f), 1.f);
    float q0 = 1.f - p0, q1 = 1.f - p1, q2 = 1.f - p2;
    b[0] = q0 * q1 * q2; b[1] = p0 * q1 * q2;
    b[2] = q0 * p1 * q2; b[3] = p0 * p1 * q2;
    b[4] = q0 * q1 * p2; b[5] = p0 * q1 * p2;
    b[6] = q0 * p1 * p2; b[7] = p0 * p1 * p2;
}

__device__ __forceinline__ void atomicMaxFloatPos(float* addr, float v) {
    atomicMax(reinterpret_cast<int*>(addr), __float_as_int(v));
}

// ---------------- degree + CSR build -----------------------------------------
__global__ void k_deg(const int* __restrict__ dst) {
    int e = blockIdx.x * blockDim.x + threadIdx.x;
    if (e < EE) atomicAdd(&d_deg[dst[e]], 1);
}

__global__ void k_scanA() {  // 256 threads/block; zeroes d_cur and d_deg (for next replay)
    __shared__ int sm[256];
    int i = blockIdx.x * 256 + threadIdx.x;
    int v = (i < NN) ? d_deg[i] : 0;
    if (i < NN) { d_cur[i] = 0; d_deg[i] = 0; }
    sm[threadIdx.x] = v;
    __syncthreads();
    for (int off = 1; off < 256; off <<= 1) {
        int t = (threadIdx.x >= off) ? sm[threadIdx.x - off] : 0;
        __syncthreads();
        sm[threadIdx.x] += t;
        __syncthreads();
    }
    if (i < NN) d_off[i] = sm[threadIdx.x] - v;  // exclusive within block
    if (threadIdx.x == 255) d_part[blockIdx.x] = sm[255];
}

__global__ void k_scanB(int nparts) {  // 1 block, 1024 threads
    __shared__ int sm[1024];
    int v = (threadIdx.x < nparts) ? d_part[threadIdx.x] : 0;
    sm[threadIdx.x] = v;
    __syncthreads();
    for (int off = 1; off < 1024; off <<= 1) {
        int t = (threadIdx.x >= off) ? sm[threadIdx.x - off] : 0;
        __syncthreads();
        sm[threadIdx.x] += t;
        __syncthreads();
    }
    if (threadIdx.x < nparts) d_pbase[threadIdx.x] = sm[threadIdx.x] - v;
}

__global__ void k_fill(const int* __restrict__ src, const int* __restrict__ dst,
                       const float* __restrict__ ea) {
    int e = blockIdx.x * blockDim.x + threadIdx.x;
    if (e < 5 * 64) d_statsAll[e] = 0.f;     // zero all conv BN stats
    if (e >= EE) return;
    int d = dst[e];
    int slot = csr_off(d) + atomicAdd(&d_cur[d], 1);
    d_esrc[slot] = src[e];
    float bs[8];
    basis8(ea[3 * e + 0], ea[3 * e + 1], ea[3 * e + 2], bs);
    float4* p = reinterpret_cast<float4*>(d_sbas + (size_t)slot * 8);
    p[0] = make_float4(bs[0], bs[1], bs[2], bs[3]);
    p[1] = make_float4(bs[4], bs[5], bs[6], bs[7]);
}

// ---------------- fused SplineConv: gather outer-product + node GEMM ----------
// out[d] = ((1/deg) * sum_e b_e (x) x_src(e)) . W_flat[8*CIN, COUT]
// Block: 256 threads = 32 sub-warps of 8 lanes (lane = kernel index s).
template <int CIN, int COUT>
__global__ __launch_bounds__(256) void k_conv(const float* __restrict__ xin,
                                              float* __restrict__ xout,
                                              const float* __restrict__ W,
                                              float* __restrict__ ostat) {
    constexpr int K = 8 * CIN;
    constexpr int KP = K + 4;          // rows stay 16B-aligned (KP % 4 == 0)
    constexpr int DB = 32;             // dsts per block
    constexpr int DS = 256 / COUT;
    constexpr int OPT = DB / DS;
    constexpr int Q2 = (CIN >= 4) ? CIN / 4 : 1;   // ulonglong2 loads per x row
    constexpr int P2 = (CIN >= 2) ? CIN / 2 : 1;   // packed T accumulators
    __shared__ float Tsh[DB * K];
    __shared__ float Wt[COUT * KP];    // transposed: Wt[c][k]
    __shared__ float ssum[32], ssq[32];
    int tid = threadIdx.x;
    for (int i = tid; i < K * COUT; i += 256) {
        int k = i / COUT, c = i % COUT;
        Wt[c * KP + k] = W[i];
    }
    if (tid < 32) { ssum[tid] = 0.f; ssq[tid] = 0.f; }
    __syncthreads();

    int sub = tid >> 3;
    int s = tid & 7;
    int d = blockIdx.x * DB + sub;
    float invdeg = 0.f;

    if constexpr (CIN == 1) {
        float T0 = 0.f;
        if (d < NN) {
            int st = csr_off(d), en = csr_end(d);
            int j = st;
            for (; j + 1 < en; j += 2) {
                int sn0 = d_esrc[j], sn1 = d_esrc[j + 1];
                float b0 = d_sbas[(size_t)j * 8 + s];
                float b1 = d_sbas[(size_t)(j + 1) * 8 + s];
                float v0 = xin[sn0], v1 = xin[sn1];
                T0 += b0 * v0 + b1 * v1;
            }
            if (j < en) {
                T0 += d_sbas[(size_t)j * 8 + s] * xin[d_esrc[j]];
            }
            invdeg = 1.f / fmaxf((float)(en - st), 1.f);
        }
        Tsh[sub * K + s] = T0 * invdeg;
    } else {
        ull Tp[P2];
#pragma unroll
        for (int i = 0; i < P2; i++) Tp[i] = 0ull;
        if (d < NN) {
            int st = csr_off(d), en = csr_end(d);
            int j = st;
            // ---- 2-edge software pipeline: batch all loads before FMAs ----
            for (; j + 1 < en; j += 2) {
                int sn0 = d_esrc[j], sn1 = d_esrc[j + 1];
                float b0 = d_sbas[(size_t)j * 8 + s];
                float b1 = d_sbas[(size_t)(j + 1) * 8 + s];
                const ulonglong2* x0 = reinterpret_cast<const ulonglong2*>(xin + (size_t)sn0 * CIN);
                const ulonglong2* x1 = reinterpret_cast<const ulonglong2*>(xin + (size_t)sn1 * CIN);
                ulonglong2 v0[Q2], v1[Q2];
#pragma unroll
                for (int q = 0; q < Q2; q++) v0[q] = x0[q];
#pragma unroll
                for (int q = 0; q < Q2; q++) v1[q] = x1[q];
                ull bb0 = pack2(b0, b0);
                ull bb1 = pack2(b1, b1);
#pragma unroll
                for (int q = 0; q < Q2; q++) {
                    Tp[2 * q + 0] = ffma2(bb0, v0[q].x, Tp[2 * q + 0]);
                    Tp[2 * q + 1] = ffma2(bb0, v0[q].y, Tp[2 * q + 1]);
                }
#pragma unroll
                for (int q = 0; q < Q2; q++) {
                    Tp[2 * q + 0] = ffma2(bb1, v1[q].x, Tp[2 * q + 0]);
                    Tp[2 * q + 1] = ffma2(bb1, v1[q].y, Tp[2 * q + 1]);
                }
            }
            if (j < en) {
                int sn0 = d_esrc[j];
                float b0 = d_sbas[(size_t)j * 8 + s];
                const ulonglong2* x0 = reinterpret_cast<const ulonglong2*>(xin + (size_t)sn0 * CIN);
                ull bb0 = pack2(b0, b0);
#pragma unroll
                for (int q = 0; q < Q2; q++) {
                    ulonglong2 v = x0[q];
                    Tp[2 * q + 0] = ffma2(bb0, v.x, Tp[2 * q + 0]);
                    Tp[2 * q + 1] = ffma2(bb0, v.y, Tp[2 * q + 1]);
                }
            }
            invdeg = 1.f / fmaxf((float)(en - st), 1.f);   // mean folded into T
        }
        ull iv2 = pack2(invdeg, invdeg);
#pragma unroll
        for (int i = 0; i < P2; i++)
            *reinterpret_cast<ull*>(&Tsh[sub * K + s * CIN + 2 * i]) = fmul2(Tp[i], iv2);
    }
    __syncthreads();

    // ---- GEMM phase (packed over k; horizontal add at end) ----
    int c = tid % COUT;
    int dl = tid / COUT;
    ull acc2a[OPT], acc2b[OPT];        // two chains per output for ILP
#pragma unroll
    for (int p = 0; p < OPT; p++) { acc2a[p] = 0ull; acc2b[p] = 0ull; }
#pragma unroll
    for (int k = 0; k < K; k += 4) {
        ulonglong2 w2 = *reinterpret_cast<const ulonglong2*>(&Wt[c * KP + k]);
#pragma unroll
        for (int p = 0; p < OPT; p++) {
            ulonglong2 t2 = *reinterpret_cast<const ulonglong2*>(&Tsh[(dl + p * DS) * K + k]);
            acc2a[p] = ffma2(w2.x, t2.x, acc2a[p]);
            acc2b[p] = ffma2(w2.y, t2.y, acc2b[p]);
        }
    }
    float ps = 0.f, pq = 0.f;
#pragma unroll
    for (int p = 0; p < OPT; p++) {
        int dd = blockIdx.x * DB + dl + p * DS;
        if (dd < NN) {
            ull t = fadd2(acc2a[p], acc2b[p]);
            float lo, hi;
            unpack2(t, lo, hi);
            float acc = lo + hi;
            xout[(size_t)dd * COUT + c] = acc;
            ps += acc; pq += acc * acc;
        }
    }
    atomicAdd(&ssum[c], ps);
    atomicAdd(&ssq[c], pq);
    __syncthreads();
    if (tid < COUT) {
        atomicAdd(&ostat[tid], ssum[tid]);
        atomicAdd(&ostat[COUT + tid], ssq[tid]);
    }
}

// ---------------- BN apply + relu (in place, vectorized, consts in prologue) --
template <int C>
__global__ void k_bnapply(float* __restrict__ xio, const float* __restrict__ stat,
                          const float* __restrict__ g, const float* __restrict__ b) {
    __shared__ float sc[C], sh[C];
    if (threadIdx.x < C) {
        float mean = stat[threadIdx.x] * (1.f / NN);
        float var = stat[C + threadIdx.x] * (1.f / NN) - mean * mean;
        float s = rsqrtf(var + EPSB) * g[threadIdx.x];
        sc[threadIdx.x] = s;
        sh[threadIdx.x] = b[threadIdx.x] - mean * s;
    }
    __syncthreads();
    int i = blockIdx.x * blockDim.x + threadIdx.x;   // float4 index
    if (i >= NN * C / 4) return;
    int cb = (i % (C / 4)) * 4;
    float4 v = reinterpret_cast<float4*>(xio)[i];
    v.x = fmaxf(v.x * sc[cb + 0] + sh[cb + 0], 0.f);
    v.y = fmaxf(v.y * sc[cb + 1] + sh[cb + 1], 0.f);
    v.z = fmaxf(v.z * sc[cb + 2] + sh[cb + 2], 0.f);
    v.w = fmaxf(v.w * sc[cb + 3] + sh[cb + 3], 0.f);
    reinterpret_cast<float4*>(xio)[i] = v;
}

// ---------------- pooling-buffer zero (replaces 7 memsets) --------------------
__global__ void k_zero() {
    int i = blockIdx.x * blockDim.x + threadIdx.x;
    int T = gridDim.x * blockDim.x;
    int* adj4 = reinterpret_cast<int*>(d_adj);
    for (int p = i; p < (MM * MM) / 4; p += T) adj4[p] = 0;
    if (i < MM * 32) d_xp[i] = 0.f;
    if (i < MM * 3) d_pp[i] = 0.f;
    if (i < MM) d_cnt[i] = 0;
    if (i < BB * GRD * 32) d_xg[i] = 0.f;
    if (i < 128) d_pstats[i] = 0.f;
    if (i == 0) { d_maxv = 0; d_nm = 0; }
}

// ---------------- voxel pooling (BN5+relu fused on read) ----------------------
__global__ void k_cluster(const float* __restrict__ pos, const int* __restrict__ batch,
                          const float* __restrict__ xin,
                          const float* __restrict__ pstat,
                          const float* __restrict__ g5, const float* __restrict__ b5) {
    __shared__ float sc[32], sh[32];
    if (threadIdx.x < 32) {
        float mean = pstat[threadIdx.x] * (1.f / NN);
        float var = pstat[32 + threadIdx.x] * (1.f / NN) - mean * mean;
        float s = rsqrtf(var + EPSB) * g5[threadIdx.x];
        sc[threadIdx.x] = s;
        sh[threadIdx.x] = b5[threadIdx.x] - mean * s;
    }
    __syncthreads();
    int n = blockIdx.x * blockDim.x + threadIdx.x;
    if (n >= NN) return;
    float p0 = pos[3 * n + 0], p1 = pos[3 * n + 1], p2 = pos[3 * n + 2];
    int cx = min(max((int)floorf(p0 / 16.0f), 0), NX_ - 1);
    int cy = min(max((int)floorf(p1 / 12.0f), 0), NY_ - 1);
    int cl = batch[n] * NCC + cy * NX_ + cx;
    d_clu[n] = cl;
    atomicAdd(&d_cnt[cl], 1);
    atomicAdd(&d_pp[cl * 3 + 0], p0);
    atomicAdd(&d_pp[cl * 3 + 1], p1);
    atomicAdd(&d_pp[cl * 3 + 2], p2);
    const float4* xr = reinterpret_cast<const float4*>(xin + (size_t)n * 32);
#pragma unroll
    for (int i = 0; i < 8; i++) {
        float4 v = xr[i];
        atomicMaxFloatPos(&d_xp[cl * 32 + 4 * i + 0], fmaxf(v.x * sc[4 * i + 0] + sh[4 * i + 0], 0.f));
        atomicMaxFloatPos(&d_xp[cl * 32 + 4 * i + 1], fmaxf(v.y * sc[4 * i + 1] + sh[4 * i + 1], 0.f));
        atomicMaxFloatPos(&d_xp[cl * 32 + 4 * i + 2], fmaxf(v.z * sc[4 * i + 2] + sh[4 * i + 2], 0.f));
        atomicMaxFloatPos(&d_xp[cl * 32 + 4 * i + 3], fmaxf(v.w * sc[4 * i + 3] + sh[4 * i + 3], 0.f));
    }
}

// ---------------- adjacency + pooled-position finalize (merged) ---------------
__global__ void k_adjpp(const int* __restrict__ src, const int* __restrict__ dst) {
    int e = blockIdx.x * blockDim.x + threadIdx.x;
    if (e < MM) {
        float c = fmaxf((float)d_cnt[e], 1.f);
        d_pp[e * 3 + 0] /= c;
        d_pp[e * 3 + 1] /= c;
        d_pp[e * 3 + 2] /= c;
        if (d_cnt[e] > 0) atomicAdd(&d_nm, 1);
    }
    if (e >= EE) return;
    int a = d_clu[src[e]], b = d_clu[dst[e]];
    if (a != b) d_adj[a * MM + b] = 1;
}

__global__ void k_maxv() {
    const int T = gridDim.x * blockDim.x;
    int t = blockIdx.x * blockDim.x + threadIdx.x;
    float mx = 0.f;
    for (int p = t; p < MM * MM; p += T) {
        if (d_adj[p]) {
            int r = p / MM, c = p % MM;
            mx = fmaxf(mx, fabsf(d_pp[c * 3 + 0] - d_pp[r * 3 + 0]));
            mx = fmaxf(mx, fabsf(d_pp[c * 3 + 1] - d_pp[r * 3 + 1]));
            mx = fmaxf(mx, fabsf(d_pp[c * 3 + 2] - d_pp[r * 3 + 2]));
        }
    }
    __shared__ float red[256];
    red[threadIdx.x] = mx;
    __syncthreads();
    for (int o = 128; o > 0; o >>= 1) {
        if (threadIdx.x < o) red[threadIdx.x] = fmaxf(red[threadIdx.x], red[threadIdx.x + o]);
        __syncthreads();
    }
    if (threadIdx.x == 0) atomicMax(&d_maxv, __float_as_int(red[0]));
}

// ---------------- pooled conv: per-node projections z = x . W[s] --------------
__global__ void k_pz(const float* __restrict__ xin, const float* __restrict__ W) {
    int t = blockIdx.x * blockDim.x + threadIdx.x;
    if (t >= MM * 8 * 32) return;
    int co = t & 31;
    int s = (t >> 5) & 7;
    int r = t >> 8;
    float acc = 0.f;
    const float* xr = &xin[r * 32];
    const float* wp = &W[s * 32 * 32 + co];
#pragma unroll
    for (int ci = 0; ci < 32; ci++) acc += xr[ci] * wp[ci * 32];
    d_pz[t] = acc;
}

// ---------------- pooled conv: per-dst aggregation + fused masked BN stats ----
__global__ void k_pconv(float* __restrict__ out, float* __restrict__ ostat) {
    int c = blockIdx.x;
    int lane = threadIdx.x & 31;
    int w = threadIdx.x >> 5;  // 8 warps
    int g = c / NCC;
    int base = g * NCC;
    float inv = 0.5f / fmaxf(__int_as_float(d_maxv), 1e-9f);
    float pc0 = d_pp[c * 3 + 0], pc1 = d_pp[c * 3 + 1], pc2 = d_pp[c * 3 + 2];
    float acc = 0.f;
    int cnt = 0;
    for (int r = base + w; r < base + NCC; r += 8) {
        if (r == c || !d_adj[r * MM + c]) continue;
        cnt++;
        float bs[8];
        basis8((pc0 - d_pp[r * 3 + 0]) * inv + 0.5f,
               (pc1 - d_pp[r * 3 + 1]) * inv + 0.5f,
               (pc2 - d_pp[r * 3 + 2]) * inv + 0.5f, bs);
        const float* z = &d_pz[r * 256];
#pragma unroll
        for (int s = 0; s < 8; s++) acc += bs[s] * z[s * 32 + lane];
    }
    __shared__ float sa[8][32];
    __shared__ int scn[8];
    sa[w][lane] = acc;
    if (lane == 0) scn[w] = cnt;
    __syncthreads();
    if (w == 0) {
        float a = 0.f;
        int k = 0;
#pragma unroll
        for (int j = 0; j < 8; j++) { a += sa[j][lane]; k += scn[j]; }
        float o = a / fmaxf((float)k, 1.f);
        out[c * 32 + lane] = o;
        if (d_cnt[c] > 0) {                      // masked BN stats, fused
            atomicAdd(&ostat[lane], o);
            atomicAdd(&ostat[32 + lane], o * o);
        }
    }
}

// ---------------- pooled BN finalize (+ optional fused MaxPoolingX) -----------
template <bool DOPOOL>
__global__ void k_pbn(const float* __restrict__ x, const float* __restrict__ stat,
                      const float* __restrict__ g, const float* __restrict__ b,
                      float* __restrict__ out) {
    int i = blockIdx.x * blockDim.x + threadIdx.x;
    if (i >= MM * 32) return;
    int c = i & 31;
    int m = i >> 5;
    float cntf = fmaxf((float)d_nm, 1.f);
    float mean = stat[c] / cntf;
    float var = stat[32 + c] / cntf - mean * mean;
    float v = (x[i] - mean) * rsqrtf(var + EPSB) * g[c] + b[c];
    bool live = d_cnt[m] > 0;
    if (!live) v = 0.f;
    v = fmaxf(v, 0.f);
    out[i] = v;
    if (DOPOOL && live) {
        int gb = m / NCC;
        int gx = min(max((int)floorf(d_pp[m * 3 + 0] / 30.0f), 0), 3);
        int gy = min(max((int)floorf(d_pp[m * 3 + 1] / 25.0f), 0), 3);
        int seg = gb * GRD + gy * 4 + gx;
        atomicMaxFloatPos(&d_xg[seg * 32 + c], v);
    }
}

__global__ void k_fc(const float* __restrict__ fcw, float* __restrict__ out) {
    int b = blockIdx.x;            // BB blocks
    int o = threadIdx.x >> 5;      // 2 warps
    int lane = threadIdx.x & 31;
    float s = 0.f;
    for (int j = lane; j < GRD * 32; j += 32)
        s += d_xg[b * GRD * 32 + j] * fcw[o * GRD * 32 + j];
#pragma unroll
    for (int off = 16; off; off >>= 1) s += __shfl_down_sync(0xffffffff, s, off);
    if (lane == 0) out[b * NOUTC + o] = s;
}

// ---------------- host orchestration -----------------------------------------
extern "C" void kernel_launch(void* const* d_in, const int* in_sizes, int n_in,
                              void* d_out, int out_size) {
    const float* x   = (const float*)d_in[0];
    const float* pos = (const float*)d_in[1];
    const float* ea  = (const float*)d_in[2];
    const float* w[7];
    const float* gm[7];
    const float* bt[7];
    for (int i = 0; i < 7; i++) {
        w[i]  = (const float*)d_in[3 + i];
        gm[i] = (const float*)d_in[10 + i];
        bt[i] = (const float*)d_in[17 + i];
    }
    const float* fcw = (const float*)d_in[24];
    const int* ei    = (const int*)d_in[25];
    const int* batch = (const int*)d_in[26];
    const int* src = ei;
    const int* dst = ei + EE;
    float* out = (float*)d_out;

    void *pxA, *pxB, *pstatsAll, *ppstats, *pxp, *pxu;
    cudaGetSymbolAddress(&pxA, d_xA);
    cudaGetSymbolAddress(&pxB, d_xB);
    cudaGetSymbolAddress(&pstatsAll, d_statsAll);
    cudaGetSymbolAddress(&ppstats, d_pstats);
    cudaGetSymbolAddress(&pxp, d_xp);
    cudaGetSymbolAddress(&pxu, d_xu);
    float* fxA = (float*)pxA;
    float* fxB = (float*)pxB;
    float* st  = (float*)pstatsAll;   // st + 64*i = stats of conv i
    float* pst = (float*)ppstats;     // pst + 64*i = pooled stats of conv 6/7

    const int TB = 256;
    const int EG = (EE + TB - 1) / TB;
    const int NG = (NN + TB - 1) / TB;
    const int SB = (NN + 255) / 256;
    const int DG = (NN + 31) / 32;

    // ---- CSR build (d_deg zero-init at load; re-zeroed by k_scanA each call) ----
    k_deg<<<EG, TB>>>(dst);
    k_scanA<<<SB, 256>>>();
    k_scanB<<<1, 1024>>>(SB);
    k_fill<<<EG, TB>>>(src, dst, ea);

    // ---- conv1..conv5 (post-BN applied in-place between convs) ----
    k_conv<1,  8 ><<<DG, 256>>>(x,   fxA, w[0], st + 0);
    k_bnapply<8 ><<<(NN * 8 / 4 + TB - 1) / TB, TB>>>(fxA, st + 0, gm[0], bt[0]);
    k_conv<8,  16><<<DG, 256>>>(fxA, fxB, w[1], st + 64);
    k_bnapply<16><<<(NN * 16 / 4 + TB - 1) / TB, TB>>>(fxB, st + 64, gm[1], bt[1]);
    k_conv<16, 16><<<DG, 256>>>(fxB, fxA, w[2], st + 128);
    k_bnapply<16><<<(NN * 16 / 4 + TB - 1) / TB, TB>>>(fxA, st + 128, gm[2], bt[2]);
    k_conv<16, 16><<<DG, 256>>>(fxA, fxB, w[3], st + 192);
    k_bnapply<16><<<(NN * 16 / 4 + TB - 1) / TB, TB>>>(fxB, st + 192, gm[3], bt[3]);
    k_conv<16, 32><<<DG, 256>>>(fxB, fxA, w[4], st + 256);
    // BN5 + relu fused into k_cluster below

    // ---- MaxPooling (voxel grid) ----
    k_zero<<<232, 256>>>();
    k_cluster<<<NG, TB>>>(pos, batch, fxA, st + 256, gm[4], bt[4]);
    k_adjpp<<<EG, TB>>>(src, dst);
    k_maxv<<<592, TB>>>();

    // ---- conv6: 32 -> 32 (pooled; stats fused in k_pconv) ----
    k_pz<<<(MM * 256 + TB - 1) / TB, TB>>>((const float*)pxp, w[5]);
    k_pconv<<<MM, 256>>>(d_xt, pst + 0);
    k_pbn<false><<<(MM * 32 + TB - 1) / TB, TB>>>(d_xt, pst + 0, gm[5], bt[5], (float*)pxu);

    // ---- conv7: 32 -> 32 (pooled; stats fused; MaxPoolingX fused in BN) ----
    k_pz<<<(MM * 256 + TB - 1) / TB, TB>>>((const float*)pxu, w[6]);
    k_pconv<<<MM, 256>>>(d_xt, pst + 64);
    k_pbn<true><<<(MM * 32 + TB - 1) / TB, TB>>>(d_xt, pst + 64, gm[6], bt[6], (float*)pxu);

    // ---- FC ----
    k_fc<<<BB, 64>>>(fcw, out);
}